// round 2
// baseline (speedup 1.0000x reference)
#include <cuda_runtime.h>

// PolyphaseDiff: resample_poly(x, up=3, down=2) with 129-tap FIR.
// out[j] = sum_{s=0}^{42} (3*h[pf+3s]) * x[i0 - s],
//   t = 64+2j, pf = t mod 3, i0 = floor(t/3)
//
// FMA-bound kernel. Each thread computes R=8 same-phase (j mod 3) consecutive
// outputs (i0 advances by 2 per output) from a circular 16-register x window,
// fed from a swizzled shared-memory tile (conflict-free for the stride-16
// lane access pattern). Results staged in shared for coalesced global stores.

#define RR 8                 // outputs per thread
#define NTAPS 43             // 129 / 3
#define THREADS 192          // 6 warps: warp w -> output-residue class w%3
#define NOUT_BLK 1536        // 3 classes * 64 threads/class * RR
#define TILE_W 1072          // x floats needed per block (+slack)
#define TILE_ALLOC (TILE_W + TILE_W / 32 + 8)

// shared-bank swizzle: lane addresses stride 16 words -> 16-way conflict;
// idx + idx/32 makes banks (m, m+16) -> conflict-free. Strictly increasing => injective.
__device__ __forceinline__ int SW(int i) { return i + (i >> 5); }

__global__ __launch_bounds__(THREADS, 8)
void poly_resample_kernel(const float* __restrict__ x,
                          const float* __restrict__ h,
                          float* __restrict__ out,
                          int N, int n_out)
{
    __shared__ float sh_x[TILE_ALLOC];
    __shared__ float sh_h[132];
    __shared__ float sh_out[NOUT_BLK];

    const int tid = threadIdx.x;
    const int Jb  = blockIdx.x * NOUT_BLK;          // first output index of block
    const int IB  = (64 + 2 * Jb) / 3 - 42;         // lowest x index any thread touches

    // taps with gain `up`=3 folded in
    for (int k = tid; k < 129; k += THREADS)
        sh_h[k] = 3.0f * h[k];

    // cooperative x tile load, zero-padded at both tensor edges, swizzled store
    for (int m = tid; m < TILE_W; m += THREADS) {
        int g = IB + m;
        float v = (g >= 0 && g < N) ? x[g] : 0.0f;
        sh_x[SW(m)] = v;
    }
    __syncthreads();

    const int wid  = tid >> 5;
    const int lane = tid & 31;
    const int p    = wid % 3;                       // j mod 3 class (uniform per warp)
    const int pf   = (1 + 2 * p) % 3;               // FILTER phase: (64+2*j0) mod 3
    const int u    = (wid / 3) * 32 + lane;         // 0..63 within class
    const int q0   = u * RR;                        // first class-local output index
    const int j0   = Jb + 3 * q0 + p;               // first global output index
    const int i0   = (64 + 2 * j0) / 3;             // top x index for output r=0
    const int li   = i0 - IB;                       // local tile index, >= 42

    // circular register window: slot (pos & 15) holds x[i0 - 42 + pos]
    float w[16];
    #pragma unroll
    for (int m = 0; m < 15; ++m)
        w[m] = sh_x[SW(li - 42 + m)];

    float acc[RR];
    #pragma unroll
    for (int r = 0; r < RR; ++r) acc[r] = 0.0f;

    // step c handles tap s = 42 - c; output r needs x at pos = c + 2r (max c+14)
    #pragma unroll
    for (int c = 0; c < NTAPS; ++c) {
        const int s = (NTAPS - 1) - c;
        const float hv = sh_h[pf + 3 * s];
        #pragma unroll
        for (int r = 0; r < RR; ++r)
            acc[r] = fmaf(hv, w[(c + 2 * r) & 15], acc[r]);
        if (c < NTAPS - 1)
            w[(c + 15) & 15] = sh_x[SW(li - 42 + c + 15)];
    }

    // stage (stride-3 pattern) then coalesced global store
    #pragma unroll
    for (int r = 0; r < RR; ++r)
        sh_out[3 * (q0 + r) + p] = acc[r];
    __syncthreads();

    for (int m = tid; m < NOUT_BLK; m += THREADS) {
        int j = Jb + m;
        if (j < n_out) out[j] = sh_out[m];
    }
}

extern "C" void kernel_launch(void* const* d_in, const int* in_sizes, int n_in,
                              void* d_out, int out_size)
{
    const float* x = (const float*)d_in[0];
    const float* h = (const float*)d_in[1];
    // d_in[2]/d_in[3] are up/down (3, 2) — specialized at compile time.
    float* out = (float*)d_out;

    const int N = in_sizes[0];
    const int n_out = out_size;
    const int grid = (n_out + NOUT_BLK - 1) / NOUT_BLK;   // 2048 for this shape

    poly_resample_kernel<<<grid, THREADS>>>(x, h, out, N, n_out);
}

// round 3
// speedup vs baseline: 1.0135x; 1.0135x over previous
#include <cuda_runtime.h>

// PolyphaseDiff: resample_poly(x, up=3, down=2), 129-tap FIR.
// out[j] = sum_{c=0}^{42} a[c]*w[c],  w[c]=x[i0-42+c],  a[c]=3*h[pf+126-3c],
//   t=64+2j, pf=t%3, i0=t/3.
//
// f32x2 formulation: acc[r] is a packed pair (even-c partial, odd-c partial).
// Tap-pair k multiplies window pair wp[k+r] = (w[2k+2r], w[2k+1+2r]) — adjacent
// elements, so the 29-pair register window needs no repacking in the loop.
// Inner loop: 21x8 fma.rn.f32x2 + 21 uniform LDS.64 tap loads. No x LDS, no ALU.

#define RR 8                 // outputs per thread
#define NPAIR 21             // 21 tap pairs + 1 tail tap = 43 taps/phase
#define THREADS 192          // 6 warps: warp w -> output-residue class w%3
#define NOUT_BLK 1536        // 3 classes * 64 threads/class * RR
#define TILE_W 1088          // x floats per block (need up to li+15 = 1081)
#define TILE_ALLOC (TILE_W + TILE_W / 32 + 8)

typedef unsigned long long u64;

// bank swizzle for stride-16 lane pattern -> conflict-free
__device__ __forceinline__ int SW(int i) { return i + (i >> 5); }

#define FMA_X2(d, a, b, c) \
    asm("fma.rn.f32x2 %0, %1, %2, %3;" : "=l"(d) : "l"(a), "l"(b), "l"(c))
#define PACK_X2(d, lo, hi) \
    asm("mov.b64 %0, {%1, %2};" : "=l"(d) : "f"(lo), "f"(hi))
#define UNPACK_X2(lo, hi, s) \
    asm("mov.b64 {%0, %1}, %2;" : "=f"(lo), "=f"(hi) : "l"(s))

__global__ __launch_bounds__(THREADS, 3)
void poly_resample_kernel(const float* __restrict__ x,
                          const float* __restrict__ h,
                          float* __restrict__ out,
                          int N, int n_out)
{
    __shared__ float sh_x[TILE_ALLOC];
    __shared__ u64   sh_a2[3 * NPAIR];   // packed tap pairs per filter phase
    __shared__ float sh_a42[3];          // tail tap (c=42) per filter phase
    __shared__ float sh_out[NOUT_BLK];

    const int tid = threadIdx.x;
    const int Jb  = blockIdx.x * NOUT_BLK;
    const int IB  = (64 + 2 * Jb) / 3 - 42;

    // pack taps: pair k of phase pf = (3h[pf+126-6k], 3h[pf+123-6k])
    if (tid < 3 * NPAIR) {
        int pf = tid / NPAIR, k = tid % NPAIR;
        float lo = 3.0f * h[pf + 126 - 6 * k];
        float hi = 3.0f * h[pf + 123 - 6 * k];
        u64 d; PACK_X2(d, lo, hi);
        sh_a2[tid] = d;
    }
    if (tid < 3) sh_a42[tid] = 3.0f * h[tid];

    // cooperative x tile, zero-padded edges, swizzled
    for (int m = tid; m < TILE_W; m += THREADS) {
        int g = IB + m;
        sh_x[SW(m)] = (g >= 0 && g < N) ? x[g] : 0.0f;
    }
    __syncthreads();

    const int wid  = tid >> 5;
    const int lane = tid & 31;
    const int p    = wid % 3;              // j mod 3 class (uniform per warp)
    const int pf   = (1 + 2 * p) % 3;      // filter phase: (64+2*j0) mod 3
    const int u    = (wid / 3) * 32 + lane;
    const int q0   = u * RR;
    const int j0   = Jb + 3 * q0 + p;
    const int i0   = (64 + 2 * j0) / 3;
    const int base = i0 - IB - 42;         // local index of w[0], >= 0

    // register window: wp[k] = (w[2k], w[2k+1]), covers w[0..57]
    u64 wp[29];
    #pragma unroll
    for (int k = 0; k < 29; ++k) {
        float lo = sh_x[SW(base + 2 * k)];
        float hi = sh_x[SW(base + 2 * k + 1)];
        PACK_X2(wp[k], lo, hi);
    }

    u64 acc[RR];
    #pragma unroll
    for (int r = 0; r < RR; ++r) acc[r] = 0ull;

    const u64* a2 = sh_a2 + pf * NPAIR;
    #pragma unroll
    for (int k = 0; k < NPAIR; ++k) {
        u64 ap = a2[k];                    // uniform per warp -> LDS.64 broadcast
        #pragma unroll
        for (int r = 0; r < RR; ++r)
            FMA_X2(acc[r], ap, wp[k + r], acc[r]);
    }

    // tail tap c=42 (needs w[42+2r] = lo half of wp[21+r]), lane combine, stage
    const float a42 = sh_a42[pf];
    #pragma unroll
    for (int r = 0; r < RR; ++r) {
        float e, o;  UNPACK_X2(e, o, acc[r]);
        float xl, xh; UNPACK_X2(xl, xh, wp[21 + r]);
        (void)xh;
        sh_out[3 * (q0 + r) + p] = fmaf(a42, xl, e + o);
    }
    __syncthreads();

    // coalesced store
    for (int m = tid; m < NOUT_BLK; m += THREADS) {
        int j = Jb + m;
        if (j < n_out) out[j] = sh_out[m];
    }
}

extern "C" void kernel_launch(void* const* d_in, const int* in_sizes, int n_in,
                              void* d_out, int out_size)
{
    const float* x = (const float*)d_in[0];
    const float* h = (const float*)d_in[1];
    float* out = (float*)d_out;

    const int N = in_sizes[0];
    const int n_out = out_size;
    const int grid = (n_out + NOUT_BLK - 1) / NOUT_BLK;   // 2048 for this shape

    poly_resample_kernel<<<grid, THREADS>>>(x, h, out, N, n_out);
}